// round 11
// baseline (speedup 1.0000x reference)
#include <cuda_runtime.h>
#include <cuda_bf16.h>
#include <cstdint>
#include <math.h>

// Problem constants
#define N_TOK 4096
#define DIN   512
#define HDIM  2048
#define NEXP  8
#define NSLOT 8192
#define SA 40    // A smem stride (bf16): 32 + 8 pad
#define SB 136   // B smem stride (bf16): 128 + 8 pad

// dynamic smem stage layout (bytes)
#define AH_OFF 0
#define AL_OFF 10240                // 128*SA*2
#define BH_OFF 20480
#define BL_OFF 29184                // 20480 + 32*SB*2
#define STAGE_BYTES 37888
#define DSMEM (2 * STAGE_BYTES)     // 75776

#define NT 512                      // threads per block (16 warps, 4x4 warp grid)

// ---------------- device scratch (~80 MB, proven-clean footprint) ----------------
__device__ int   g_counts[NEXP];
__device__ int   g_list[NEXP * NSLOT];
__device__ int   g_is64;
__device__ float g_zero[HDIM];                 // stays all-zero
__device__ float g_h[(size_t)NSLOT * HDIM];    // 64 MB hidden (fp32)
__device__ float g_y[(size_t)NSLOT * DIN];     // 16 MB per-slot outputs

// ---------------- PTX macros: scalar operands only ----------------
__device__ __forceinline__ uint32_t smem_u32(const void* p) {
    uint32_t a;
    asm("{ .reg .u64 t; cvta.to.shared.u64 t, %1; cvt.u32.u64 %0, t; }"
        : "=r"(a) : "l"(p));
    return a;
}
#define LDM_X4(r0, r1, r2, r3, a) \
    asm volatile("ldmatrix.sync.aligned.m8n8.x4.shared.b16 {%0,%1,%2,%3}, [%4];" \
                 : "=r"(r0), "=r"(r1), "=r"(r2), "=r"(r3) : "r"(a))
#define LDM_X2T(r0, r1, a) \
    asm volatile("ldmatrix.sync.aligned.m8n8.x2.trans.shared.b16 {%0,%1}, [%2];" \
                 : "=r"(r0), "=r"(r1) : "r"(a))
#define MMA16816(c0, c1, c2, c3, a0, a1, a2, a3, b0, b1) \
    asm volatile("mma.sync.aligned.m16n8k16.row.col.f32.bf16.bf16.f32 " \
                 "{%0,%1,%2,%3}, {%4,%5,%6,%7}, {%8,%9}, {%0,%1,%2,%3};" \
                 : "+f"(c0), "+f"(c1), "+f"(c2), "+f"(c3) \
                 : "r"(a0), "r"(a1), "r"(a2), "r"(a3), "r"(b0), "r"(b1))
// 3-term accumulate: hi*hi + lo*hi + hi*lo
#define MMA3(C, AH, AL, BH, BL) do { \
    MMA16816(C.x, C.y, C.z, C.w, AH.x, AH.y, AH.z, AH.w, BH.x, BH.y); \
    MMA16816(C.x, C.y, C.z, C.w, AL.x, AL.y, AL.z, AL.w, BH.x, BH.y); \
    MMA16816(C.x, C.y, C.z, C.w, AH.x, AH.y, AH.z, AH.w, BL.x, BL.y); \
} while (0)

// ---------------- dispatch ----------------
__global__ void k_reset(const int* idx32) {
    int t = threadIdx.x;
    if (t < NEXP) g_counts[t] = 0;
    if (t == 0) {
        int allz = 1;
        #pragma unroll
        for (int i = 1; i < 32; i += 2)
            if (idx32[i] != 0) allz = 0;
        g_is64 = allz;
    }
}
__global__ void k_build(const void* idxp) {
    int s = blockIdx.x * blockDim.x + threadIdx.x;
    if (s >= NSLOT) return;
    int e = g_is64 ? (int)((const long long*)idxp)[s] : ((const int*)idxp)[s];
    int pos = atomicAdd(&g_counts[e], 1);
    g_list[e * NSLOT + pos] = s;
}

__device__ __forceinline__ float gelu_tanh(float v) {
    float u = 0.7978845608028654f * (v + 0.044715f * v * v * v);
    return 0.5f * v * (1.0f + tanhf(u));
}

// ---------------- fused-convert tensor-core grouped GEMM ----------------
// 512 threads, 16 warps (4x4 grid), warp tile 32x32; LDG prefetch + double buffer.
// MODE 1: h = gelu(gather(x) @ W1[e] + b1[e])   K=512,  Ntot=2048, A row = slot>>1
// MODE 2: y = gather(h) @ W2[e] + b2[e]         K=2048, Ntot=512,  A row = slot
template <int MODE>
__global__ __launch_bounds__(NT, 1)
void k_mma(const float* __restrict__ Asrc_in, const float* __restrict__ W,
           const float* __restrict__ bias) {
    extern __shared__ __align__(16) char dsm[];
    __shared__ const float* s_aptr[128];
    __shared__ int s_slot[128];

    const int e   = blockIdx.z;
    const int cnt = g_counts[e];
    const int m0  = blockIdx.y * 128;
    if (m0 >= cnt) return;
    const int n0  = blockIdx.x * 128;
    const int tid = threadIdx.x;
    const int lane = tid & 31, w = tid >> 5;
    const int wm = w & 3, wn = w >> 2;          // 4x4 warp grid, warp tile 32x32

    constexpr int K    = (MODE == 1) ? DIN : HDIM;
    constexpr int Ntot = (MODE == 1) ? HDIM : DIN;
    const float* Asrc = (MODE == 1) ? Asrc_in : (const float*)g_h;
    const float* Bsrc = W + (size_t)e * K * Ntot;

    if (tid < 128) {
        int m = m0 + tid;
        if (m < cnt) {
            int s = g_list[e * NSLOT + m];
            s_slot[tid] = s;
            int r = (MODE == 1) ? (s >> 1) : s;
            s_aptr[tid] = Asrc + (size_t)r * K;
        } else {
            s_slot[tid] = -1;
            s_aptr[tid] = g_zero;
        }
    }
    __syncthreads();

    const uint32_t dyn0 = smem_u32(dsm);

    // warp tile 32x32: accum i in {0,1} (16-row mma), j in {0..3} (8-col mma)
    float4 c00 = make_float4(0.f, 0.f, 0.f, 0.f), c01 = c00, c02 = c00, c03 = c00;
    float4 c10 = c00, c11 = c00, c12 = c00, c13 = c00;

    // prefetch registers (named scalars): 2 A units + 2 B units per thread
    float4 pa0, pa1, pb0, pb1;

#define LDG_A(V, U, K0) do { \
    int unit_ = tid + (U) * NT; \
    int r_ = unit_ >> 3, p_ = unit_ & 7; \
    V = *(const float4*)(s_aptr[r_] + (K0) + p_ * 4); \
} while (0)
#define LDG_B(V, U, K0) do { \
    int unit_ = tid + (U) * NT; \
    int r_ = unit_ >> 5, p_ = unit_ & 31; \
    V = *(const float4*)(Bsrc + (size_t)((K0) + r_) * Ntot + n0 + p_ * 4); \
} while (0)
#define PREF(K0) do { \
    LDG_A(pa0, 0, K0); LDG_A(pa1, 1, K0); \
    LDG_B(pb0, 0, K0); LDG_B(pb1, 1, K0); \
} while (0)
#define ST_A(V, U, SBASE) do { \
    int unit_ = tid + (U) * NT; \
    int r_ = unit_ >> 3, p_ = unit_ & 7; \
    __nv_bfloat16 h0_ = __float2bfloat16(V.x), h1_ = __float2bfloat16(V.y); \
    __nv_bfloat16 h2_ = __float2bfloat16(V.z), h3_ = __float2bfloat16(V.w); \
    int o_ = (r_ * SA + p_ * 4) * 2; \
    *(__nv_bfloat162*)((SBASE) + AH_OFF + o_)     = __nv_bfloat162{h0_, h1_}; \
    *(__nv_bfloat162*)((SBASE) + AH_OFF + o_ + 4) = __nv_bfloat162{h2_, h3_}; \
    *(__nv_bfloat162*)((SBASE) + AL_OFF + o_) = __nv_bfloat162{ \
        __float2bfloat16(V.x - __bfloat162float(h0_)), \
        __float2bfloat16(V.y - __bfloat162float(h1_))}; \
    *(__nv_bfloat162*)((SBASE) + AL_OFF + o_ + 4) = __nv_bfloat162{ \
        __float2bfloat16(V.z - __bfloat162float(h2_)), \
        __float2bfloat16(V.w - __bfloat162float(h3_))}; \
} while (0)
#define ST_B(V, U, SBASE) do { \
    int unit_ = tid + (U) * NT; \
    int r_ = unit_ >> 5, p_ = unit_ & 31; \
    __nv_bfloat16 h0_ = __float2bfloat16(V.x), h1_ = __float2bfloat16(V.y); \
    __nv_bfloat16 h2_ = __float2bfloat16(V.z), h3_ = __float2bfloat16(V.w); \
    int o_ = (r_ * SB + p_ * 4) * 2; \
    *(__nv_bfloat162*)((SBASE) + BH_OFF + o_)     = __nv_bfloat162{h0_, h1_}; \
    *(__nv_bfloat162*)((SBASE) + BH_OFF + o_ + 4) = __nv_bfloat162{h2_, h3_}; \
    *(__nv_bfloat162*)((SBASE) + BL_OFF + o_) = __nv_bfloat162{ \
        __float2bfloat16(V.x - __bfloat162float(h0_)), \
        __float2bfloat16(V.y - __bfloat162float(h1_))}; \
    *(__nv_bfloat162*)((SBASE) + BL_OFF + o_ + 4) = __nv_bfloat162{ \
        __float2bfloat16(V.z - __bfloat162float(h2_)), \
        __float2bfloat16(V.w - __bfloat162float(h3_))}; \
} while (0)

    constexpr int nch = K / 32;
    PREF(0);

    for (int ch = 0; ch < nch; ch++) {
        char* sb = dsm + (ch & 1) * STAGE_BYTES;
        ST_A(pa0, 0, sb); ST_A(pa1, 1, sb);
        ST_B(pb0, 0, sb); ST_B(pb1, 1, sb);
        __syncthreads();   // single barrier per chunk (double-buffered)

        if (ch + 1 < nch) PREF((ch + 1) * 32);

        const uint32_t sAh0 = dyn0 + (ch & 1) * STAGE_BYTES + AH_OFF;
        const uint32_t sAl0 = dyn0 + (ch & 1) * STAGE_BYTES + AL_OFF;
        const uint32_t sBh0 = dyn0 + (ch & 1) * STAGE_BYTES + BH_OFF;
        const uint32_t sBl0 = dyn0 + (ch & 1) * STAGE_BYTES + BL_OFF;

        #pragma unroll
        for (int kk = 0; kk < 32; kk += 16) {
            const uint32_t aoff = ((wm * 32 + (lane & 15)) * SA + kk + (lane >> 4) * 8) * 2;
            uint4 Ah0, Ah1, Al0, Al1;
            LDM_X4(Ah0.x, Ah0.y, Ah0.z, Ah0.w, sAh0 + aoff);
            LDM_X4(Ah1.x, Ah1.y, Ah1.z, Ah1.w, sAh0 + aoff + 16 * SA * 2);
            LDM_X4(Al0.x, Al0.y, Al0.z, Al0.w, sAl0 + aoff);
            LDM_X4(Al1.x, Al1.y, Al1.z, Al1.w, sAl0 + aoff + 16 * SA * 2);

            const uint32_t boff = ((kk + (lane & 15)) * SB + wn * 32) * 2;
            uint2 Bh0, Bh1, Bh2, Bh3, Bl0, Bl1, Bl2, Bl3;
            LDM_X2T(Bh0.x, Bh0.y, sBh0 + boff);
            LDM_X2T(Bh1.x, Bh1.y, sBh0 + boff + 16);
            LDM_X2T(Bh2.x, Bh2.y, sBh0 + boff + 32);
            LDM_X2T(Bh3.x, Bh3.y, sBh0 + boff + 48);
            LDM_X2T(Bl0.x, Bl0.y, sBl0 + boff);
            LDM_X2T(Bl1.x, Bl1.y, sBl0 + boff + 16);
            LDM_X2T(Bl2.x, Bl2.y, sBl0 + boff + 32);
            LDM_X2T(Bl3.x, Bl3.y, sBl0 + boff + 48);

            MMA3(c00, Ah0, Al0, Bh0, Bl0); MMA3(c01, Ah0, Al0, Bh1, Bl1);
            MMA3(c02, Ah0, Al0, Bh2, Bl2); MMA3(c03, Ah0, Al0, Bh3, Bl3);
            MMA3(c10, Ah1, Al1, Bh0, Bl0); MMA3(c11, Ah1, Al1, Bh1, Bl1);
            MMA3(c12, Ah1, Al1, Bh2, Bl2); MMA3(c13, Ah1, Al1, Bh3, Bl3);
        }
        // no trailing barrier: next chunk writes the OTHER buffer.
    }
#undef PREF
#undef LDG_A
#undef LDG_B
#undef ST_A
#undef ST_B

    // ---- epilogue ----
    const float* bptr = bias + (size_t)e * Ntot + n0;
#define EPI(C, I, J) do { \
    int r0_ = wm * 32 + (I) * 16 + (lane >> 2); \
    int s0_ = s_slot[r0_], s1_ = s_slot[r0_ + 8]; \
    int col_ = wn * 32 + (J) * 8 + (lane & 3) * 2; \
    float b0_ = bptr[col_], b1_ = bptr[col_ + 1]; \
    if (MODE == 1) { \
        if (s0_ >= 0) { \
            float2 o_ = make_float2(gelu_tanh(C.x + b0_), gelu_tanh(C.y + b1_)); \
            *(float2*)(g_h + (size_t)s0_ * HDIM + n0 + col_) = o_; \
        } \
        if (s1_ >= 0) { \
            float2 o_ = make_float2(gelu_tanh(C.z + b0_), gelu_tanh(C.w + b1_)); \
            *(float2*)(g_h + (size_t)s1_ * HDIM + n0 + col_) = o_; \
        } \
    } else { \
        if (s0_ >= 0) \
            *(float2*)(g_y + (size_t)s0_ * DIN + n0 + col_) = make_float2(C.x + b0_, C.y + b1_); \
        if (s1_ >= 0) \
            *(float2*)(g_y + (size_t)s1_ * DIN + n0 + col_) = make_float2(C.z + b0_, C.w + b1_); \
    } \
} while (0)
    EPI(c00, 0, 0); EPI(c01, 0, 1); EPI(c02, 0, 2); EPI(c03, 0, 3);
    EPI(c10, 1, 0); EPI(c11, 1, 1); EPI(c12, 1, 2); EPI(c13, 1, 3);
#undef EPI
}

// ---------------- combine + loss tail ----------------
__global__ void k_comb(const float* __restrict__ p, float* __restrict__ out) {
    int i = blockIdx.x * blockDim.x + threadIdx.x;
    if (i >= N_TOK * DIN / 4) return;
    int t = i / (DIN / 4);
    int d4 = i % (DIN / 4);
    float p0 = p[t * 2], p1 = p[t * 2 + 1];
    float4 y0 = *(const float4*)(g_y + (size_t)(2 * t) * DIN + d4 * 4);
    float4 y1 = *(const float4*)(g_y + (size_t)(2 * t + 1) * DIN + d4 * 4);
    float4 o;
    o.x = p0 * y0.x + p1 * y1.x;
    o.y = p0 * y0.y + p1 * y1.y;
    o.z = p0 * y0.z + p1 * y1.z;
    o.w = p0 * y0.w + p1 * y1.w;
    *(float4*)(out + (size_t)i * 4) = o;
}
__global__ void k_tail(float* __restrict__ out, int begin, int total) {
    int i = begin + blockIdx.x * blockDim.x + threadIdx.x;
    if (i < total) out[i] = 0.0f;
}

extern "C" void kernel_launch(void* const* d_in, const int* in_sizes, int n_in,
                              void* d_out, int out_size) {
    const float* x    = (const float*)d_in[0];
    const float* prob = (const float*)d_in[1];
    const void*  idx  = d_in[2];
    const float* W1   = (const float*)d_in[3];
    const float* b1   = (const float*)d_in[4];
    const float* W2   = (const float*)d_in[5];
    const float* b2   = (const float*)d_in[6];
    float* out = (float*)d_out;

    static int attr_done = 0;
    if (!attr_done) {
        cudaFuncSetAttribute(k_mma<1>, cudaFuncAttributeMaxDynamicSharedMemorySize, DSMEM);
        cudaFuncSetAttribute(k_mma<2>, cudaFuncAttributeMaxDynamicSharedMemorySize, DSMEM);
        attr_done = 1;
    }

    k_reset<<<1, 32>>>((const int*)idx);
    k_build<<<NSLOT / 256, 256>>>(idx);

    k_mma<1><<<dim3(HDIM / 128, NSLOT / 128, NEXP), NT, DSMEM>>>(x, W1, b1);
    k_mma<2><<<dim3(DIN / 128, NSLOT / 128, NEXP), NT, DSMEM>>>(nullptr, W2, b2);

    k_comb<<<(N_TOK * DIN / 4 + 255) / 256, 256>>>(prob, out);
    int tail = out_size - N_TOK * DIN;
    if (tail > 0)
        k_tail<<<(tail + 255) / 256, 256>>>(out, N_TOK * DIN, out_size);
    (void)in_sizes; (void)n_in;
}

// round 13
// speedup vs baseline: 1.3269x; 1.3269x over previous
#include <cuda_runtime.h>
#include <cuda_fp16.h>
#include <cstdint>
#include <math.h>

// Problem constants
#define N_TOK 4096
#define DIN   512
#define HDIM  2048
#define NEXP  8
#define NSLOT 8192
#define SA 40    // A smem stride (fp16): 32 + 8 pad
#define SB 136   // B smem stride (fp16): 128 + 8 pad

// dynamic smem stage layout (bytes): Ah, Al, Bh (no Bl — B is single fp16)
#define AH_OFF 0
#define AL_OFF 10240                // 128*SA*2
#define BH_OFF 20480
#define STAGE_BYTES 29184           // 20480 + 32*SB*2
#define DSMEM (2 * STAGE_BYTES)     // 58368

#define NT 512                      // 16 warps, 4x4 warp grid

// ---------------- device scratch (~80 MB, proven-clean footprint) ----------------
__device__ int   g_counts[NEXP];
__device__ int   g_list[NEXP * NSLOT];
__device__ int   g_is64;
__device__ float g_zero[HDIM];                 // stays all-zero
__device__ float g_h[(size_t)NSLOT * HDIM];    // 64 MB hidden (fp32)
__device__ float g_y[(size_t)NSLOT * DIN];     // 16 MB per-slot outputs

// ---------------- PTX macros: scalar operands only ----------------
__device__ __forceinline__ uint32_t smem_u32(const void* p) {
    uint32_t a;
    asm("{ .reg .u64 t; cvta.to.shared.u64 t, %1; cvt.u32.u64 %0, t; }"
        : "=r"(a) : "l"(p));
    return a;
}
#define LDM_X4(r0, r1, r2, r3, a) \
    asm volatile("ldmatrix.sync.aligned.m8n8.x4.shared.b16 {%0,%1,%2,%3}, [%4];" \
                 : "=r"(r0), "=r"(r1), "=r"(r2), "=r"(r3) : "r"(a))
#define LDM_X2T(r0, r1, a) \
    asm volatile("ldmatrix.sync.aligned.m8n8.x2.trans.shared.b16 {%0,%1}, [%2];" \
                 : "=r"(r0), "=r"(r1) : "r"(a))
#define MMA16816(c0, c1, c2, c3, a0, a1, a2, a3, b0, b1) \
    asm volatile("mma.sync.aligned.m16n8k16.row.col.f32.f16.f16.f32 " \
                 "{%0,%1,%2,%3}, {%4,%5,%6,%7}, {%8,%9}, {%0,%1,%2,%3};" \
                 : "+f"(c0), "+f"(c1), "+f"(c2), "+f"(c3) \
                 : "r"(a0), "r"(a1), "r"(a2), "r"(a3), "r"(b0), "r"(b1))
// 2-term accumulate: A_hi*B + A_lo*B  (A split to fp16 hi/lo; B single fp16)
#define MMA2(C, AH, AL, BH) do { \
    MMA16816(C.x, C.y, C.z, C.w, AH.x, AH.y, AH.z, AH.w, BH.x, BH.y); \
    MMA16816(C.x, C.y, C.z, C.w, AL.x, AL.y, AL.z, AL.w, BH.x, BH.y); \
} while (0)

// ---------------- dispatch ----------------
__global__ void k_reset(const int* idx32) {
    int t = threadIdx.x;
    if (t < NEXP) g_counts[t] = 0;
    if (t == 0) {
        int allz = 1;
        #pragma unroll
        for (int i = 1; i < 32; i += 2)
            if (idx32[i] != 0) allz = 0;
        g_is64 = allz;
    }
}
__global__ void k_build(const void* idxp) {
    int s = blockIdx.x * blockDim.x + threadIdx.x;
    if (s >= NSLOT) return;
    int e = g_is64 ? (int)((const long long*)idxp)[s] : ((const int*)idxp)[s];
    int pos = atomicAdd(&g_counts[e], 1);
    g_list[e * NSLOT + pos] = s;
}

__device__ __forceinline__ float gelu_tanh(float v) {
    float u = 0.7978845608028654f * (v + 0.044715f * v * v * v);
    return 0.5f * v * (1.0f + tanhf(u));
}

// ---------------- fused-convert tensor-core grouped GEMM ----------------
// 512 threads, 16 warps (4x4 grid), warp tile 32x32; LDG prefetch + double buffer.
// fp16 2-term: A split hi/lo (residual 2^-22), B single fp16 (err <= 2^-12).
// MODE 1: h = gelu(gather(x) @ W1[e] + b1[e])   K=512,  Ntot=2048, A row = slot>>1
// MODE 2: y = gather(h) @ W2[e] + b2[e]         K=2048, Ntot=512,  A row = slot
template <int MODE>
__global__ __launch_bounds__(NT, 1)
void k_mma(const float* __restrict__ Asrc_in, const float* __restrict__ W,
           const float* __restrict__ bias) {
    extern __shared__ __align__(16) char dsm[];
    __shared__ const float* s_aptr[128];
    __shared__ int s_slot[128];

    const int e   = blockIdx.z;
    const int cnt = g_counts[e];
    const int m0  = blockIdx.y * 128;
    if (m0 >= cnt) return;
    const int n0  = blockIdx.x * 128;
    const int tid = threadIdx.x;
    const int lane = tid & 31, w = tid >> 5;
    const int wm = w & 3, wn = w >> 2;          // 4x4 warp grid, warp tile 32x32

    constexpr int K    = (MODE == 1) ? DIN : HDIM;
    constexpr int Ntot = (MODE == 1) ? HDIM : DIN;
    const float* Asrc = (MODE == 1) ? Asrc_in : (const float*)g_h;
    const float* Bsrc = W + (size_t)e * K * Ntot;

    if (tid < 128) {
        int m = m0 + tid;
        if (m < cnt) {
            int s = g_list[e * NSLOT + m];
            s_slot[tid] = s;
            int r = (MODE == 1) ? (s >> 1) : s;
            s_aptr[tid] = Asrc + (size_t)r * K;
        } else {
            s_slot[tid] = -1;
            s_aptr[tid] = g_zero;
        }
    }
    __syncthreads();

    const uint32_t dyn0 = smem_u32(dsm);

    // warp tile 32x32: accum i in {0,1}, j in {0..3}
    float4 c00 = make_float4(0.f, 0.f, 0.f, 0.f), c01 = c00, c02 = c00, c03 = c00;
    float4 c10 = c00, c11 = c00, c12 = c00, c13 = c00;

    // prefetch registers (named scalars)
    float4 pa0, pa1, pb0, pb1;

#define LDG_A(V, U, K0) do { \
    int unit_ = tid + (U) * NT; \
    int r_ = unit_ >> 3, p_ = unit_ & 7; \
    V = *(const float4*)(s_aptr[r_] + (K0) + p_ * 4); \
} while (0)
#define LDG_B(V, U, K0) do { \
    int unit_ = tid + (U) * NT; \
    int r_ = unit_ >> 5, p_ = unit_ & 31; \
    V = *(const float4*)(Bsrc + (size_t)((K0) + r_) * Ntot + n0 + p_ * 4); \
} while (0)
#define PREF(K0) do { \
    LDG_A(pa0, 0, K0); LDG_A(pa1, 1, K0); \
    LDG_B(pb0, 0, K0); LDG_B(pb1, 1, K0); \
} while (0)
#define ST_A(V, U, SBASE) do { \
    int unit_ = tid + (U) * NT; \
    int r_ = unit_ >> 3, p_ = unit_ & 7; \
    __half h0_ = __float2half_rn(V.x), h1_ = __float2half_rn(V.y); \
    __half h2_ = __float2half_rn(V.z), h3_ = __float2half_rn(V.w); \
    int o_ = (r_ * SA + p_ * 4) * 2; \
    *(__half2*)((SBASE) + AH_OFF + o_)     = __halves2half2(h0_, h1_); \
    *(__half2*)((SBASE) + AH_OFF + o_ + 4) = __halves2half2(h2_, h3_); \
    *(__half2*)((SBASE) + AL_OFF + o_) = __halves2half2( \
        __float2half_rn(V.x - __half2float(h0_)), \
        __float2half_rn(V.y - __half2float(h1_))); \
    *(__half2*)((SBASE) + AL_OFF + o_ + 4) = __halves2half2( \
        __float2half_rn(V.z - __half2float(h2_)), \
        __float2half_rn(V.w - __half2float(h3_))); \
} while (0)
#define ST_B(V, U, SBASE) do { \
    int unit_ = tid + (U) * NT; \
    int r_ = unit_ >> 5, p_ = unit_ & 31; \
    int o_ = (r_ * SB + p_ * 4) * 2; \
    *(__half2*)((SBASE) + BH_OFF + o_) = __halves2half2( \
        __float2half_rn(V.x), __float2half_rn(V.y)); \
    *(__half2*)((SBASE) + BH_OFF + o_ + 4) = __halves2half2( \
        __float2half_rn(V.z), __float2half_rn(V.w)); \
} while (0)

    constexpr int nch = K / 32;
    PREF(0);

    for (int ch = 0; ch < nch; ch++) {
        char* sb = dsm + (ch & 1) * STAGE_BYTES;
        ST_A(pa0, 0, sb); ST_A(pa1, 1, sb);
        ST_B(pb0, 0, sb); ST_B(pb1, 1, sb);
        __syncthreads();   // single barrier per chunk (double-buffered)

        if (ch + 1 < nch) PREF((ch + 1) * 32);

        const uint32_t sAh0 = dyn0 + (ch & 1) * STAGE_BYTES + AH_OFF;
        const uint32_t sAl0 = dyn0 + (ch & 1) * STAGE_BYTES + AL_OFF;
        const uint32_t sBh0 = dyn0 + (ch & 1) * STAGE_BYTES + BH_OFF;

        #pragma unroll
        for (int kk = 0; kk < 32; kk += 16) {
            const uint32_t aoff = ((wm * 32 + (lane & 15)) * SA + kk + (lane >> 4) * 8) * 2;
            uint4 Ah0, Ah1, Al0, Al1;
            LDM_X4(Ah0.x, Ah0.y, Ah0.z, Ah0.w, sAh0 + aoff);
            LDM_X4(Ah1.x, Ah1.y, Ah1.z, Ah1.w, sAh0 + aoff + 16 * SA * 2);
            LDM_X4(Al0.x, Al0.y, Al0.z, Al0.w, sAl0 + aoff);
            LDM_X4(Al1.x, Al1.y, Al1.z, Al1.w, sAl0 + aoff + 16 * SA * 2);

            const uint32_t boff = ((kk + (lane & 15)) * SB + wn * 32) * 2;
            uint2 Bh0, Bh1, Bh2, Bh3;
            LDM_X2T(Bh0.x, Bh0.y, sBh0 + boff);
            LDM_X2T(Bh1.x, Bh1.y, sBh0 + boff + 16);
            LDM_X2T(Bh2.x, Bh2.y, sBh0 + boff + 32);
            LDM_X2T(Bh3.x, Bh3.y, sBh0 + boff + 48);

            MMA2(c00, Ah0, Al0, Bh0); MMA2(c01, Ah0, Al0, Bh1);
            MMA2(c02, Ah0, Al0, Bh2); MMA2(c03, Ah0, Al0, Bh3);
            MMA2(c10, Ah1, Al1, Bh0); MMA2(c11, Ah1, Al1, Bh1);
            MMA2(c12, Ah1, Al1, Bh2); MMA2(c13, Ah1, Al1, Bh3);
        }
        // no trailing barrier: next chunk writes the OTHER buffer.
    }
#undef PREF
#undef LDG_A
#undef LDG_B
#undef ST_A
#undef ST_B

    // ---- epilogue ----
    const float* bptr = bias + (size_t)e * Ntot + n0;
#define EPI(C, I, J) do { \
    int r0_ = wm * 32 + (I) * 16 + (lane >> 2); \
    int s0_ = s_slot[r0_], s1_ = s_slot[r0_ + 8]; \
    int col_ = wn * 32 + (J) * 8 + (lane & 3) * 2; \
    float b0_ = bptr[col_], b1_ = bptr[col_ + 1]; \
    if (MODE == 1) { \
        if (s0_ >= 0) { \
            float2 o_ = make_float2(gelu_tanh(C.x + b0_), gelu_tanh(C.y + b1_)); \
            *(float2*)(g_h + (size_t)s0_ * HDIM + n0 + col_) = o_; \
        } \
        if (s1_ >= 0) { \
            float2 o_ = make_float2(gelu_tanh(C.z + b0_), gelu_tanh(C.w + b1_)); \
            *(float2*)(g_h + (size_t)s1_ * HDIM + n0 + col_) = o_; \
        } \
    } else { \
        if (s0_ >= 0) \
            *(float2*)(g_y + (size_t)s0_ * DIN + n0 + col_) = make_float2(C.x + b0_, C.y + b1_); \
        if (s1_ >= 0) \
            *(float2*)(g_y + (size_t)s1_ * DIN + n0 + col_) = make_float2(C.z + b0_, C.w + b1_); \
    } \
} while (0)
    EPI(c00, 0, 0); EPI(c01, 0, 1); EPI(c02, 0, 2); EPI(c03, 0, 3);
    EPI(c10, 1, 0); EPI(c11, 1, 1); EPI(c12, 1, 2); EPI(c13, 1, 3);
#undef EPI
}

// ---------------- combine + loss tail ----------------
__global__ void k_comb(const float* __restrict__ p, float* __restrict__ out) {
    int i = blockIdx.x * blockDim.x + threadIdx.x;
    if (i >= N_TOK * DIN / 4) return;
    int t = i / (DIN / 4);
    int d4 = i % (DIN / 4);
    float p0 = p[t * 2], p1 = p[t * 2 + 1];
    float4 y0 = *(const float4*)(g_y + (size_t)(2 * t) * DIN + d4 * 4);
    float4 y1 = *(const float4*)(g_y + (size_t)(2 * t + 1) * DIN + d4 * 4);
    float4 o;
    o.x = p0 * y0.x + p1 * y1.x;
    o.y = p0 * y0.y + p1 * y1.y;
    o.z = p0 * y0.z + p1 * y1.z;
    o.w = p0 * y0.w + p1 * y1.w;
    *(float4*)(out + (size_t)i * 4) = o;
}
__global__ void k_tail(float* __restrict__ out, int begin, int total) {
    int i = begin + blockIdx.x * blockDim.x + threadIdx.x;
    if (i < total) out[i] = 0.0f;
}

extern "C" void kernel_launch(void* const* d_in, const int* in_sizes, int n_in,
                              void* d_out, int out_size) {
    const float* x    = (const float*)d_in[0];
    const float* prob = (const float*)d_in[1];
    const void*  idx  = d_in[2];
    const float* W1   = (const float*)d_in[3];
    const float* b1   = (const float*)d_in[4];
    const float* W2   = (const float*)d_in[5];
    const float* b2   = (const float*)d_in[6];
    float* out = (float*)d_out;

    static int attr_done = 0;
    if (!attr_done) {
        cudaFuncSetAttribute(k_mma<1>, cudaFuncAttributeMaxDynamicSharedMemorySize, DSMEM);
        cudaFuncSetAttribute(k_mma<2>, cudaFuncAttributeMaxDynamicSharedMemorySize, DSMEM);
        attr_done = 1;
    }

    k_reset<<<1, 32>>>((const int*)idx);
    k_build<<<NSLOT / 256, 256>>>(idx);

    k_mma<1><<<dim3(HDIM / 128, NSLOT / 128, NEXP), NT, DSMEM>>>(x, W1, b1);
    k_mma<2><<<dim3(DIN / 128, NSLOT / 128, NEXP), NT, DSMEM>>>(nullptr, W2, b2);

    k_comb<<<(N_TOK * DIN / 4 + 255) / 256, 256>>>(prob, out);
    int tail = out_size - N_TOK * DIN;
    if (tail > 0)
        k_tail<<<(tail + 255) / 256, 256>>>(out, N_TOK * DIN, out_size);
    (void)in_sizes; (void)n_in;
}

// round 14
// speedup vs baseline: 1.3437x; 1.0126x over previous
#include <cuda_runtime.h>
#include <cuda_fp16.h>
#include <cstdint>
#include <math.h>

// Problem constants
#define N_TOK 4096
#define DIN   512
#define HDIM  2048
#define NEXP  8
#define NSLOT 8192
#define SA 40    // A smem stride (fp16): 32 + 8 pad
#define SB 136   // B smem stride (fp16): 128 + 8 pad

// dynamic smem stage layout (bytes): Ah, Bh (plain fp16, no splits)
#define AH_OFF 0
#define BH_OFF 10240                // 128*SA*2
#define STAGE_BYTES 18944           // 10240 + 32*SB*2
#define DSMEM (2 * STAGE_BYTES)     // 37888

#define NT 512                      // 16 warps, 4x4 warp grid

// ---------------- device scratch (~80 MB, proven-clean footprint) ----------------
__device__ int   g_counts[NEXP];
__device__ int   g_list[NEXP * NSLOT];
__device__ int   g_is64;
__device__ float g_zero[HDIM];                 // stays all-zero
__device__ float g_h[(size_t)NSLOT * HDIM];    // 64 MB hidden (fp32)
__device__ float g_y[(size_t)NSLOT * DIN];     // 16 MB per-slot outputs

// ---------------- PTX macros: scalar operands only ----------------
__device__ __forceinline__ uint32_t smem_u32(const void* p) {
    uint32_t a;
    asm("{ .reg .u64 t; cvta.to.shared.u64 t, %1; cvt.u32.u64 %0, t; }"
        : "=r"(a) : "l"(p));
    return a;
}
#define LDM_X4(r0, r1, r2, r3, a) \
    asm volatile("ldmatrix.sync.aligned.m8n8.x4.shared.b16 {%0,%1,%2,%3}, [%4];" \
                 : "=r"(r0), "=r"(r1), "=r"(r2), "=r"(r3) : "r"(a))
#define LDM_X2T(r0, r1, a) \
    asm volatile("ldmatrix.sync.aligned.m8n8.x2.trans.shared.b16 {%0,%1}, [%2];" \
                 : "=r"(r0), "=r"(r1) : "r"(a))
#define MMA16816(c0, c1, c2, c3, a0, a1, a2, a3, b0, b1) \
    asm volatile("mma.sync.aligned.m16n8k16.row.col.f32.f16.f16.f32 " \
                 "{%0,%1,%2,%3}, {%4,%5,%6,%7}, {%8,%9}, {%0,%1,%2,%3};" \
                 : "+f"(c0), "+f"(c1), "+f"(c2), "+f"(c3) \
                 : "r"(a0), "r"(a1), "r"(a2), "r"(a3), "r"(b0), "r"(b1))
#define MMA1(C, AH, BH) \
    MMA16816(C.x, C.y, C.z, C.w, AH.x, AH.y, AH.z, AH.w, BH.x, BH.y)

// ---------------- dispatch ----------------
__global__ void k_reset(const int* idx32) {
    int t = threadIdx.x;
    if (t < NEXP) g_counts[t] = 0;
    if (t == 0) {
        int allz = 1;
        #pragma unroll
        for (int i = 1; i < 32; i += 2)
            if (idx32[i] != 0) allz = 0;
        g_is64 = allz;
    }
}
__global__ void k_build(const void* idxp) {
    int s = blockIdx.x * blockDim.x + threadIdx.x;
    if (s >= NSLOT) return;
    int e = g_is64 ? (int)((const long long*)idxp)[s] : ((const int*)idxp)[s];
    int pos = atomicAdd(&g_counts[e], 1);
    g_list[e * NSLOT + pos] = s;
}

__device__ __forceinline__ float gelu_tanh(float v) {
    float u = 0.7978845608028654f * (v + 0.044715f * v * v * v);
    return 0.5f * v * (1.0f + tanhf(u));
}

// ---------------- fused-convert tensor-core grouped GEMM ----------------
// 512 threads, 16 warps (4x4 grid), warp tile 32x32; LDG prefetch + double buffer.
// Plain fp16 operands (rel err ~4e-4 total, calibrated from the 2-term run).
// MODE 1: h = gelu(gather(x) @ W1[e] + b1[e])   K=512,  Ntot=2048, A row = slot>>1
// MODE 2: y = gather(h) @ W2[e] + b2[e]         K=2048, Ntot=512,  A row = slot
template <int MODE>
__global__ __launch_bounds__(NT, 1)
void k_mma(const float* __restrict__ Asrc_in, const float* __restrict__ W,
           const float* __restrict__ bias) {
    extern __shared__ __align__(16) char dsm[];
    __shared__ const float* s_aptr[128];
    __shared__ int s_slot[128];

    const int e   = blockIdx.z;
    const int cnt = g_counts[e];
    const int m0  = blockIdx.y * 128;
    if (m0 >= cnt) return;
    const int n0  = blockIdx.x * 128;
    const int tid = threadIdx.x;
    const int lane = tid & 31, w = tid >> 5;
    const int wm = w & 3, wn = w >> 2;          // 4x4 warp grid, warp tile 32x32

    constexpr int K    = (MODE == 1) ? DIN : HDIM;
    constexpr int Ntot = (MODE == 1) ? HDIM : DIN;
    const float* Asrc = (MODE == 1) ? Asrc_in : (const float*)g_h;
    const float* Bsrc = W + (size_t)e * K * Ntot;

    if (tid < 128) {
        int m = m0 + tid;
        if (m < cnt) {
            int s = g_list[e * NSLOT + m];
            s_slot[tid] = s;
            int r = (MODE == 1) ? (s >> 1) : s;
            s_aptr[tid] = Asrc + (size_t)r * K;
        } else {
            s_slot[tid] = -1;
            s_aptr[tid] = g_zero;
        }
    }
    __syncthreads();

    const uint32_t dyn0 = smem_u32(dsm);

    // warp tile 32x32: accum i in {0,1}, j in {0..3}
    float4 c00 = make_float4(0.f, 0.f, 0.f, 0.f), c01 = c00, c02 = c00, c03 = c00;
    float4 c10 = c00, c11 = c00, c12 = c00, c13 = c00;

    // prefetch registers (named scalars)
    float4 pa0, pa1, pb0, pb1;

#define LDG_A(V, U, K0) do { \
    int unit_ = tid + (U) * NT; \
    int r_ = unit_ >> 3, p_ = unit_ & 7; \
    V = *(const float4*)(s_aptr[r_] + (K0) + p_ * 4); \
} while (0)
#define LDG_B(V, U, K0) do { \
    int unit_ = tid + (U) * NT; \
    int r_ = unit_ >> 5, p_ = unit_ & 31; \
    V = *(const float4*)(Bsrc + (size_t)((K0) + r_) * Ntot + n0 + p_ * 4); \
} while (0)
#define PREF(K0) do { \
    LDG_A(pa0, 0, K0); LDG_A(pa1, 1, K0); \
    LDG_B(pb0, 0, K0); LDG_B(pb1, 1, K0); \
} while (0)
#define ST_A(V, U, SBASE) do { \
    int unit_ = tid + (U) * NT; \
    int r_ = unit_ >> 3, p_ = unit_ & 7; \
    int o_ = (r_ * SA + p_ * 4) * 2; \
    *(__half2*)((SBASE) + AH_OFF + o_) = __halves2half2( \
        __float2half_rn(V.x), __float2half_rn(V.y)); \
    *(__half2*)((SBASE) + AH_OFF + o_ + 4) = __halves2half2( \
        __float2half_rn(V.z), __float2half_rn(V.w)); \
} while (0)
#define ST_B(V, U, SBASE) do { \
    int unit_ = tid + (U) * NT; \
    int r_ = unit_ >> 5, p_ = unit_ & 31; \
    int o_ = (r_ * SB + p_ * 4) * 2; \
    *(__half2*)((SBASE) + BH_OFF + o_) = __halves2half2( \
        __float2half_rn(V.x), __float2half_rn(V.y)); \
    *(__half2*)((SBASE) + BH_OFF + o_ + 4) = __halves2half2( \
        __float2half_rn(V.z), __float2half_rn(V.w)); \
} while (0)

    constexpr int nch = K / 32;
    PREF(0);

    for (int ch = 0; ch < nch; ch++) {
        char* sb = dsm + (ch & 1) * STAGE_BYTES;
        ST_A(pa0, 0, sb); ST_A(pa1, 1, sb);
        ST_B(pb0, 0, sb); ST_B(pb1, 1, sb);
        __syncthreads();   // single barrier per chunk (double-buffered)

        if (ch + 1 < nch) PREF((ch + 1) * 32);

        const uint32_t sAh0 = dyn0 + (ch & 1) * STAGE_BYTES + AH_OFF;
        const uint32_t sBh0 = dyn0 + (ch & 1) * STAGE_BYTES + BH_OFF;

        #pragma unroll
        for (int kk = 0; kk < 32; kk += 16) {
            const uint32_t aoff = ((wm * 32 + (lane & 15)) * SA + kk + (lane >> 4) * 8) * 2;
            uint4 Ah0, Ah1;
            LDM_X4(Ah0.x, Ah0.y, Ah0.z, Ah0.w, sAh0 + aoff);
            LDM_X4(Ah1.x, Ah1.y, Ah1.z, Ah1.w, sAh0 + aoff + 16 * SA * 2);

            const uint32_t boff = ((kk + (lane & 15)) * SB + wn * 32) * 2;
            uint2 Bh0, Bh1, Bh2, Bh3;
            LDM_X2T(Bh0.x, Bh0.y, sBh0 + boff);
            LDM_X2T(Bh1.x, Bh1.y, sBh0 + boff + 16);
            LDM_X2T(Bh2.x, Bh2.y, sBh0 + boff + 32);
            LDM_X2T(Bh3.x, Bh3.y, sBh0 + boff + 48);

            MMA1(c00, Ah0, Bh0); MMA1(c01, Ah0, Bh1);
            MMA1(c02, Ah0, Bh2); MMA1(c03, Ah0, Bh3);
            MMA1(c10, Ah1, Bh0); MMA1(c11, Ah1, Bh1);
            MMA1(c12, Ah1, Bh2); MMA1(c13, Ah1, Bh3);
        }
        // no trailing barrier: next chunk writes the OTHER buffer.
    }
#undef PREF
#undef LDG_A
#undef LDG_B
#undef ST_A
#undef ST_B

    // ---- epilogue ----
    const float* bptr = bias + (size_t)e * Ntot + n0;
#define EPI(C, I, J) do { \
    int r0_ = wm * 32 + (I) * 16 + (lane >> 2); \
    int s0_ = s_slot[r0_], s1_ = s_slot[r0_ + 8]; \
    int col_ = wn * 32 + (J) * 8 + (lane & 3) * 2; \
    float b0_ = bptr[col_], b1_ = bptr[col_ + 1]; \
    if (MODE == 1) { \
        if (s0_ >= 0) { \
            float2 o_ = make_float2(gelu_tanh(C.x + b0_), gelu_tanh(C.y + b1_)); \
            *(float2*)(g_h + (size_t)s0_ * HDIM + n0 + col_) = o_; \
        } \
        if (s1_ >= 0) { \
            float2 o_ = make_float2(gelu_tanh(C.z + b0_), gelu_tanh(C.w + b1_)); \
            *(float2*)(g_h + (size_t)s1_ * HDIM + n0 + col_) = o_; \
        } \
    } else { \
        if (s0_ >= 0) \
            *(float2*)(g_y + (size_t)s0_ * DIN + n0 + col_) = make_float2(C.x + b0_, C.y + b1_); \
        if (s1_ >= 0) \
            *(float2*)(g_y + (size_t)s1_ * DIN + n0 + col_) = make_float2(C.z + b0_, C.w + b1_); \
    } \
} while (0)
    EPI(c00, 0, 0); EPI(c01, 0, 1); EPI(c02, 0, 2); EPI(c03, 0, 3);
    EPI(c10, 1, 0); EPI(c11, 1, 1); EPI(c12, 1, 2); EPI(c13, 1, 3);
#undef EPI
}

// ---------------- combine + loss tail ----------------
__global__ void k_comb(const float* __restrict__ p, float* __restrict__ out) {
    int i = blockIdx.x * blockDim.x + threadIdx.x;
    if (i >= N_TOK * DIN / 4) return;
    int t = i / (DIN / 4);
    int d4 = i % (DIN / 4);
    float p0 = p[t * 2], p1 = p[t * 2 + 1];
    float4 y0 = *(const float4*)(g_y + (size_t)(2 * t) * DIN + d4 * 4);
    float4 y1 = *(const float4*)(g_y + (size_t)(2 * t + 1) * DIN + d4 * 4);
    float4 o;
    o.x = p0 * y0.x + p1 * y1.x;
    o.y = p0 * y0.y + p1 * y1.y;
    o.z = p0 * y0.z + p1 * y1.z;
    o.w = p0 * y0.w + p1 * y1.w;
    *(float4*)(out + (size_t)i * 4) = o;
}
__global__ void k_tail(float* __restrict__ out, int begin, int total) {
    int i = begin + blockIdx.x * blockDim.x + threadIdx.x;
    if (i < total) out[i] = 0.0f;
}

extern "C" void kernel_launch(void* const* d_in, const int* in_sizes, int n_in,
                              void* d_out, int out_size) {
    const float* x    = (const float*)d_in[0];
    const float* prob = (const float*)d_in[1];
    const void*  idx  = d_in[2];
    const float* W1   = (const float*)d_in[3];
    const float* b1   = (const float*)d_in[4];
    const float* W2   = (const float*)d_in[5];
    const float* b2   = (const float*)d_in[6];
    float* out = (float*)d_out;

    static int attr_done = 0;
    if (!attr_done) {
        cudaFuncSetAttribute(k_mma<1>, cudaFuncAttributeMaxDynamicSharedMemorySize, DSMEM);
        cudaFuncSetAttribute(k_mma<2>, cudaFuncAttributeMaxDynamicSharedMemorySize, DSMEM);
        attr_done = 1;
    }

    k_reset<<<1, 32>>>((const int*)idx);
    k_build<<<NSLOT / 256, 256>>>(idx);

    k_mma<1><<<dim3(HDIM / 128, NSLOT / 128, NEXP), NT, DSMEM>>>(x, W1, b1);
    k_mma<2><<<dim3(DIN / 128, NSLOT / 128, NEXP), NT, DSMEM>>>(nullptr, W2, b2);

    k_comb<<<(N_TOK * DIN / 4 + 255) / 256, 256>>>(prob, out);
    int tail = out_size - N_TOK * DIN;
    if (tail > 0)
        k_tail<<<(tail + 255) / 256, 256>>>(out, N_TOK * DIN, out_size);
    (void)in_sizes; (void)n_in;
}

// round 16
// speedup vs baseline: 1.5701x; 1.1685x over previous
#include <cuda_runtime.h>
#include <cuda_fp16.h>
#include <cstdint>
#include <math.h>

// Problem constants
#define N_TOK 4096
#define DIN   512
#define HDIM  2048
#define NEXP  8
#define NSLOT 8192
#define SA 40    // A smem stride (fp16): 32 + 8 pad
#define SB 136   // B smem stride (fp16): 128 + 8 pad

// dynamic smem stage layout (bytes): Ah, Bh (plain fp16)
#define AH_OFF 0
#define BH_OFF 10240                // 128*SA*2
#define STAGE_BYTES 18944           // 10240 + 32*SB*2
#define DSMEM (2 * STAGE_BYTES)     // 37888

#define NT 512                      // 16 warps, 4x4 warp grid

// ---------------- device scratch (~80 MB, proven-clean footprint) ----------------
__device__ int   g_counts[NEXP];
__device__ int   g_list[NEXP * NSLOT];
__device__ int   g_is64;
__device__ float g_zero[HDIM];                 // stays all-zero
__device__ float g_h[(size_t)NSLOT * HDIM];    // 64 MB hidden (fp32)
__device__ float g_y[(size_t)NSLOT * DIN];     // 16 MB per-slot outputs

// ---------------- PTX macros: scalar operands only ----------------
__device__ __forceinline__ uint32_t smem_u32(const void* p) {
    uint32_t a;
    asm("{ .reg .u64 t; cvta.to.shared.u64 t, %1; cvt.u32.u64 %0, t; }"
        : "=r"(a) : "l"(p));
    return a;
}
#define LDM_X4(r0, r1, r2, r3, a) \
    asm volatile("ldmatrix.sync.aligned.m8n8.x4.shared.b16 {%0,%1,%2,%3}, [%4];" \
                 : "=r"(r0), "=r"(r1), "=r"(r2), "=r"(r3) : "r"(a))
#define LDM_X2T(r0, r1, a) \
    asm volatile("ldmatrix.sync.aligned.m8n8.x2.trans.shared.b16 {%0,%1}, [%2];" \
                 : "=r"(r0), "=r"(r1) : "r"(a))
#define MMA16816(c0, c1, c2, c3, a0, a1, a2, a3, b0, b1) \
    asm volatile("mma.sync.aligned.m16n8k16.row.col.f32.f16.f16.f32 " \
                 "{%0,%1,%2,%3}, {%4,%5,%6,%7}, {%8,%9}, {%0,%1,%2,%3};" \
                 : "+f"(c0), "+f"(c1), "+f"(c2), "+f"(c3) \
                 : "r"(a0), "r"(a1), "r"(a2), "r"(a3), "r"(b0), "r"(b1))
#define MMA1(C, AH, BH) \
    MMA16816(C.x, C.y, C.z, C.w, AH.x, AH.y, AH.z, AH.w, BH.x, BH.y)

// ---------------- dispatch ----------------
__global__ void k_reset(const int* idx32) {
    int t = threadIdx.x;
    if (t < NEXP) g_counts[t] = 0;
    if (t == 0) {
        int allz = 1;
        #pragma unroll
        for (int i = 1; i < 32; i += 2)
            if (idx32[i] != 0) allz = 0;
        g_is64 = allz;
    }
}
__global__ void k_build(const void* idxp) {
    int s = blockIdx.x * blockDim.x + threadIdx.x;
    if (s >= NSLOT) return;
    int e = g_is64 ? (int)((const long long*)idxp)[s] : ((const int*)idxp)[s];
    int pos = atomicAdd(&g_counts[e], 1);
    g_list[e * NSLOT + pos] = s;
}

__device__ __forceinline__ float gelu_tanh(float v) {
    float u = 0.7978845608028654f * (v + 0.044715f * v * v * v);
    return 0.5f * v * (1.0f + tanhf(u));
}

// ---------------- fused-convert tensor-core grouped GEMM ----------------
// 512 threads, 16 warps (4x4 grid), warp tile 32x32; distance-2 LDG prefetch
// (two register sets P/Q) + double-buffered smem, one barrier per chunk.
// Plain fp16 operands (rel err ~4e-4 measured).
// MODE 1: h = gelu(gather(x) @ W1[e] + b1[e])   K=512,  Ntot=2048, A row = slot>>1
// MODE 2: y = gather(h) @ W2[e] + b2[e]         K=2048, Ntot=512,  A row = slot
template <int MODE>
__global__ __launch_bounds__(NT, 1)
void k_mma(const float* __restrict__ Asrc_in, const float* __restrict__ W,
           const float* __restrict__ bias) {
    extern __shared__ __align__(16) char dsm[];
    __shared__ const float* s_aptr[128];
    __shared__ int s_slot[128];

    const int e   = blockIdx.z;
    const int cnt = g_counts[e];
    const int m0  = blockIdx.y * 128;
    if (m0 >= cnt) return;
    const int n0  = blockIdx.x * 128;
    const int tid = threadIdx.x;
    const int lane = tid & 31, w = tid >> 5;
    const int wm = w & 3, wn = w >> 2;          // 4x4 warp grid, warp tile 32x32

    constexpr int K    = (MODE == 1) ? DIN : HDIM;
    constexpr int Ntot = (MODE == 1) ? HDIM : DIN;
    const float* Asrc = (MODE == 1) ? Asrc_in : (const float*)g_h;
    const float* Bsrc = W + (size_t)e * K * Ntot;

    if (tid < 128) {
        int m = m0 + tid;
        if (m < cnt) {
            int s = g_list[e * NSLOT + m];
            s_slot[tid] = s;
            int r = (MODE == 1) ? (s >> 1) : s;
            s_aptr[tid] = Asrc + (size_t)r * K;
        } else {
            s_slot[tid] = -1;
            s_aptr[tid] = g_zero;
        }
    }
    __syncthreads();

    const uint32_t dyn0 = smem_u32(dsm);

    // warp tile 32x32: accum i in {0,1}, j in {0..3}
    float4 c00 = make_float4(0.f, 0.f, 0.f, 0.f), c01 = c00, c02 = c00, c03 = c00;
    float4 c10 = c00, c11 = c00, c12 = c00, c13 = c00;

    // TWO prefetch register sets (P and Q) -> LDG consume distance = 2 chunks
    float4 pa0, pa1, pb0, pb1;   // set P
    float4 qa0, qa1, qb0, qb1;   // set Q

#define LDG_A(V, U, K0) do { \
    int unit_ = tid + (U) * NT; \
    int r_ = unit_ >> 3, p_ = unit_ & 7; \
    V = *(const float4*)(s_aptr[r_] + (K0) + p_ * 4); \
} while (0)
#define LDG_B(V, U, K0) do { \
    int unit_ = tid + (U) * NT; \
    int r_ = unit_ >> 5, p_ = unit_ & 31; \
    V = *(const float4*)(Bsrc + (size_t)((K0) + r_) * Ntot + n0 + p_ * 4); \
} while (0)
#define PREF_P(K0) do { \
    LDG_A(pa0, 0, K0); LDG_A(pa1, 1, K0); \
    LDG_B(pb0, 0, K0); LDG_B(pb1, 1, K0); \
} while (0)
#define PREF_Q(K0) do { \
    LDG_A(qa0, 0, K0); LDG_A(qa1, 1, K0); \
    LDG_B(qb0, 0, K0); LDG_B(qb1, 1, K0); \
} while (0)
#define ST_A(V, U, SBASE) do { \
    int unit_ = tid + (U) * NT; \
    int r_ = unit_ >> 3, p_ = unit_ & 7; \
    int o_ = (r_ * SA + p_ * 4) * 2; \
    *(__half2*)((SBASE) + AH_OFF + o_) = __halves2half2( \
        __float2half_rn(V.x), __float2half_rn(V.y)); \
    *(__half2*)((SBASE) + AH_OFF + o_ + 4) = __halves2half2( \
        __float2half_rn(V.z), __float2half_rn(V.w)); \
} while (0)
#define ST_B(V, U, SBASE) do { \
    int unit_ = tid + (U) * NT; \
    int r_ = unit_ >> 5, p_ = unit_ & 31; \
    int o_ = (r_ * SB + p_ * 4) * 2; \
    *(__half2*)((SBASE) + BH_OFF + o_) = __halves2half2( \
        __float2half_rn(V.x), __float2half_rn(V.y)); \
    *(__half2*)((SBASE) + BH_OFF + o_ + 4) = __halves2half2( \
        __float2half_rn(V.z), __float2half_rn(V.w)); \
} while (0)

    constexpr int nch = K / 32;     // 16 (mode 1) or 64 (mode 2); >= 2
    PREF_P(0);
    PREF_Q(32);

    for (int ch = 0; ch < nch; ch++) {
        char* sb = dsm + (ch & 1) * STAGE_BYTES;
        // drain the set holding chunk ch (P for even ch, Q for odd ch)
        if ((ch & 1) == 0) {
            ST_A(pa0, 0, sb); ST_A(pa1, 1, sb);
            ST_B(pb0, 0, sb); ST_B(pb1, 1, sb);
        } else {
            ST_A(qa0, 0, sb); ST_A(qa1, 1, sb);
            ST_B(qb0, 0, sb); ST_B(qb1, 1, sb);
        }
        __syncthreads();   // single barrier per chunk (double-buffered smem)

        // refill the just-freed set with chunk ch+2: ~2 chunk-times to complete
        if (ch + 2 < nch) {
            if ((ch & 1) == 0) PREF_P((ch + 2) * 32);
            else               PREF_Q((ch + 2) * 32);
        }

        const uint32_t sAh0 = dyn0 + (ch & 1) * STAGE_BYTES + AH_OFF;
        const uint32_t sBh0 = dyn0 + (ch & 1) * STAGE_BYTES + BH_OFF;

        #pragma unroll
        for (int kk = 0; kk < 32; kk += 16) {
            const uint32_t aoff = ((wm * 32 + (lane & 15)) * SA + kk + (lane >> 4) * 8) * 2;
            uint4 Ah0, Ah1;
            LDM_X4(Ah0.x, Ah0.y, Ah0.z, Ah0.w, sAh0 + aoff);
            LDM_X4(Ah1.x, Ah1.y, Ah1.z, Ah1.w, sAh0 + aoff + 16 * SA * 2);

            const uint32_t boff = ((kk + (lane & 15)) * SB + wn * 32) * 2;
            uint2 Bh0, Bh1, Bh2, Bh3;
            LDM_X2T(Bh0.x, Bh0.y, sBh0 + boff);
            LDM_X2T(Bh1.x, Bh1.y, sBh0 + boff + 16);
            LDM_X2T(Bh2.x, Bh2.y, sBh0 + boff + 32);
            LDM_X2T(Bh3.x, Bh3.y, sBh0 + boff + 48);

            MMA1(c00, Ah0, Bh0); MMA1(c01, Ah0, Bh1);
            MMA1(c02, Ah0, Bh2); MMA1(c03, Ah0, Bh3);
            MMA1(c10, Ah1, Bh0); MMA1(c11, Ah1, Bh1);
            MMA1(c12, Ah1, Bh2); MMA1(c13, Ah1, Bh3);
        }
        // no trailing barrier: next chunk writes the OTHER smem buffer.
    }
#undef PREF_P
#undef PREF_Q
#undef LDG_A
#undef LDG_B
#undef ST_A
#undef ST_B

    // ---- epilogue ----
    const float* bptr = bias + (size_t)e * Ntot + n0;
#define EPI(C, I, J) do { \
    int r0_ = wm * 32 + (I) * 16 + (lane >> 2); \
    int s0_ = s_slot[r0_], s1_ = s_slot[r0_ + 8]; \
    int col_ = wn * 32 + (J) * 8 + (lane & 3) * 2; \
    float b0_ = bptr[col_], b1_ = bptr[col_ + 1]; \
    if (MODE == 1) { \
        if (s0_ >= 0) { \
            float2 o_ = make_float2(gelu_tanh(C.x + b0_), gelu_tanh(C.y + b1_)); \
            *(float2*)(g_h + (size_t)s0_ * HDIM + n0 + col_) = o_; \
        } \
        if (s1_ >= 0) { \
            float2 o_ = make_float2(gelu_tanh(C.z + b0_), gelu_tanh(C.w + b1_)); \
            *(float2*)(g_h + (size_t)s1_ * HDIM + n0 + col_) = o_; \
        } \
    } else { \
        if (s0_ >= 0) \
            *(float2*)(g_y + (size_t)s0_ * DIN + n0 + col_) = make_float2(C.x + b0_, C.y + b1_); \
        if (s1_ >= 0) \
            *(float2*)(g_y + (size_t)s1_ * DIN + n0 + col_) = make_float2(C.z + b0_, C.w + b1_); \
    } \
} while (0)
    EPI(c00, 0, 0); EPI(c01, 0, 1); EPI(c02, 0, 2); EPI(c03, 0, 3);
    EPI(c10, 1, 0); EPI(c11, 1, 1); EPI(c12, 1, 2); EPI(c13, 1, 3);
#undef EPI
}

// ---------------- combine + loss tail ----------------
__global__ void k_comb(const float* __restrict__ p, float* __restrict__ out) {
    int i = blockIdx.x * blockDim.x + threadIdx.x;
    if (i >= N_TOK * DIN / 4) return;
    int t = i / (DIN / 4);
    int d4 = i % (DIN / 4);
    float p0 = p[t * 2], p1 = p[t * 2 + 1];
    float4 y0 = *(const float4*)(g_y + (size_t)(2 * t) * DIN + d4 * 4);
    float4 y1 = *(const float4*)(g_y + (size_t)(2 * t + 1) * DIN + d4 * 4);
    float4 o;
    o.x = p0 * y0.x + p1 * y1.x;
    o.y = p0 * y0.y + p1 * y1.y;
    o.z = p0 * y0.z + p1 * y1.z;
    o.w = p0 * y0.w + p1 * y1.w;
    *(float4*)(out + (size_t)i * 4) = o;
}
__global__ void k_tail(float* __restrict__ out, int begin, int total) {
    int i = begin + blockIdx.x * blockDim.x + threadIdx.x;
    if (i < total) out[i] = 0.0f;
}

extern "C" void kernel_launch(void* const* d_in, const int* in_sizes, int n_in,
                              void* d_out, int out_size) {
    const float* x    = (const float*)d_in[0];
    const float* prob = (const float*)d_in[1];
    const void*  idx  = d_in[2];
    const float* W1   = (const float*)d_in[3];
    const float* b1   = (const float*)d_in[4];
    const float* W2   = (const float*)d_in[5];
    const float* b2   = (const float*)d_in[6];
    float* out = (float*)d_out;

    static int attr_done = 0;
    if (!attr_done) {
        cudaFuncSetAttribute(k_mma<1>, cudaFuncAttributeMaxDynamicSharedMemorySize, DSMEM);
        cudaFuncSetAttribute(k_mma<2>, cudaFuncAttributeMaxDynamicSharedMemorySize, DSMEM);
        attr_done = 1;
    }

    k_reset<<<1, 32>>>((const int*)idx);
    k_build<<<NSLOT / 256, 256>>>(idx);

    k_mma<1><<<dim3(HDIM / 128, NSLOT / 128, NEXP), NT, DSMEM>>>(x, W1, b1);
    k_mma<2><<<dim3(DIN / 128, NSLOT / 128, NEXP), NT, DSMEM>>>(nullptr, W2, b2);

    k_comb<<<(N_TOK * DIN / 4 + 255) / 256, 256>>>(prob, out);
    int tail = out_size - N_TOK * DIN;
    if (tail > 0)
        k_tail<<<(tail + 255) / 256, 256>>>(out, N_TOK * DIN, out_size);
    (void)in_sizes; (void)n_in;
}

// round 17
// speedup vs baseline: 1.5928x; 1.0145x over previous
#include <cuda_runtime.h>
#include <cuda_fp16.h>
#include <cstdint>
#include <math.h>

// Problem constants
#define N_TOK 4096
#define DIN   512
#define HDIM  2048
#define NEXP  8
#define NSLOT 8192
#define SA 40    // A smem stride (fp16): 32 + 8 pad
#define SB 136   // B smem stride (fp16): 128 + 8 pad

// dynamic smem stage layout (bytes): Ah, Bh (plain fp16)
#define AH_OFF 0
#define BH_OFF 10240                // 128*SA*2
#define STAGE_BYTES 18944           // 10240 + 32*SB*2
#define DSMEM (2 * STAGE_BYTES)     // 37888

#define NT 512                      // 16 warps, 4x4 warp grid

// ---------------- device scratch (~80 MB, proven-clean footprint) ----------------
__device__ int   g_counts[NEXP];
__device__ int   g_list[NEXP * NSLOT];
__device__ int   g_is64;
__device__ float g_zero[HDIM];                 // stays all-zero
__device__ float g_h[(size_t)NSLOT * HDIM];    // 64 MB hidden (fp32)
__device__ float g_y[(size_t)NSLOT * DIN];     // 16 MB per-slot outputs

// ---------------- PTX macros: scalar operands only ----------------
__device__ __forceinline__ uint32_t smem_u32(const void* p) {
    uint32_t a;
    asm("{ .reg .u64 t; cvta.to.shared.u64 t, %1; cvt.u32.u64 %0, t; }"
        : "=r"(a) : "l"(p));
    return a;
}
#define LDM_X4(r0, r1, r2, r3, a) \
    asm volatile("ldmatrix.sync.aligned.m8n8.x4.shared.b16 {%0,%1,%2,%3}, [%4];" \
                 : "=r"(r0), "=r"(r1), "=r"(r2), "=r"(r3) : "r"(a))
#define LDM_X4T(r0, r1, r2, r3, a) \
    asm volatile("ldmatrix.sync.aligned.m8n8.x4.trans.shared.b16 {%0,%1,%2,%3}, [%4];" \
                 : "=r"(r0), "=r"(r1), "=r"(r2), "=r"(r3) : "r"(a))
#define MMA16816(c0, c1, c2, c3, a0, a1, a2, a3, b0, b1) \
    asm volatile("mma.sync.aligned.m16n8k16.row.col.f32.f16.f16.f32 " \
                 "{%0,%1,%2,%3}, {%4,%5,%6,%7}, {%8,%9}, {%0,%1,%2,%3};" \
                 : "+f"(c0), "+f"(c1), "+f"(c2), "+f"(c3) \
                 : "r"(a0), "r"(a1), "r"(a2), "r"(a3), "r"(b0), "r"(b1))
#define MMA1(C, AH, BH) \
    MMA16816(C.x, C.y, C.z, C.w, AH.x, AH.y, AH.z, AH.w, BH.x, BH.y)
// pack two fp32 -> one fp16x2 register (x -> low half, y -> high half)
#define PACK2(u, x, y) \
    asm("cvt.rn.f16x2.f32 %0, %1, %2;" : "=r"(u) : "f"(y), "f"(x))
#define STS64(addr, u0, u1) \
    asm volatile("st.shared.v2.b32 [%0], {%1, %2};" :: "r"(addr), "r"(u0), "r"(u1))

// ---------------- dispatch ----------------
__global__ void k_reset(const int* idx32) {
    int t = threadIdx.x;
    if (t < NEXP) g_counts[t] = 0;
    if (t == 0) {
        int allz = 1;
        #pragma unroll
        for (int i = 1; i < 32; i += 2)
            if (idx32[i] != 0) allz = 0;
        g_is64 = allz;
    }
}
__global__ void k_build(const void* idxp) {
    int s = blockIdx.x * blockDim.x + threadIdx.x;
    if (s >= NSLOT) return;
    int e = g_is64 ? (int)((const long long*)idxp)[s] : ((const int*)idxp)[s];
    int pos = atomicAdd(&g_counts[e], 1);
    g_list[e * NSLOT + pos] = s;
}

__device__ __forceinline__ float gelu_tanh(float v) {
    float u = 0.7978845608028654f * (v + 0.044715f * v * v * v);
    return 0.5f * v * (1.0f + tanhf(u));
}

// ---------------- fused-convert tensor-core grouped GEMM ----------------
// 512 threads, 16 warps (4x4 grid), warp tile 32x32; distance-2 LDG prefetch
// (two register sets P/Q) + double-buffered smem, one barrier per chunk.
// MIO-slimmed: v2.b32 smem stores w/ f16x2 packing; B via ldmatrix.x4.trans.
// MODE 1: h = gelu(gather(x) @ W1[e] + b1[e])   K=512,  Ntot=2048, A row = slot>>1
// MODE 2: y = gather(h) @ W2[e] + b2[e]         K=2048, Ntot=512,  A row = slot
template <int MODE>
__global__ __launch_bounds__(NT, 1)
void k_mma(const float* __restrict__ Asrc_in, const float* __restrict__ W,
           const float* __restrict__ bias) {
    extern __shared__ __align__(16) char dsm[];
    __shared__ const float* s_aptr[128];
    __shared__ int s_slot[128];

    const int e   = blockIdx.z;
    const int cnt = g_counts[e];
    const int m0  = blockIdx.y * 128;
    if (m0 >= cnt) return;
    const int n0  = blockIdx.x * 128;
    const int tid = threadIdx.x;
    const int lane = tid & 31, w = tid >> 5;
    const int wm = w & 3, wn = w >> 2;          // 4x4 warp grid, warp tile 32x32

    constexpr int K    = (MODE == 1) ? DIN : HDIM;
    constexpr int Ntot = (MODE == 1) ? HDIM : DIN;
    const float* Asrc = (MODE == 1) ? Asrc_in : (const float*)g_h;
    const float* Bsrc = W + (size_t)e * K * Ntot;

    if (tid < 128) {
        int m = m0 + tid;
        if (m < cnt) {
            int s = g_list[e * NSLOT + m];
            s_slot[tid] = s;
            int r = (MODE == 1) ? (s >> 1) : s;
            s_aptr[tid] = Asrc + (size_t)r * K;
        } else {
            s_slot[tid] = -1;
            s_aptr[tid] = g_zero;
        }
    }
    __syncthreads();

    const uint32_t dyn0 = smem_u32(dsm);

    // warp tile 32x32: accum i in {0,1}, j in {0..3}
    float4 c00 = make_float4(0.f, 0.f, 0.f, 0.f), c01 = c00, c02 = c00, c03 = c00;
    float4 c10 = c00, c11 = c00, c12 = c00, c13 = c00;

    // TWO prefetch register sets (P and Q) -> LDG consume distance = 2 chunks
    float4 pa0, pa1, pb0, pb1;   // set P
    float4 qa0, qa1, qb0, qb1;   // set Q

#define LDG_A(V, U, K0) do { \
    int unit_ = tid + (U) * NT; \
    int r_ = unit_ >> 3, p_ = unit_ & 7; \
    V = *(const float4*)(s_aptr[r_] + (K0) + p_ * 4); \
} while (0)
#define LDG_B(V, U, K0) do { \
    int unit_ = tid + (U) * NT; \
    int r_ = unit_ >> 5, p_ = unit_ & 31; \
    V = *(const float4*)(Bsrc + (size_t)((K0) + r_) * Ntot + n0 + p_ * 4); \
} while (0)
#define PREF_P(K0) do { \
    LDG_A(pa0, 0, K0); LDG_A(pa1, 1, K0); \
    LDG_B(pb0, 0, K0); LDG_B(pb1, 1, K0); \
} while (0)
#define PREF_Q(K0) do { \
    LDG_A(qa0, 0, K0); LDG_A(qa1, 1, K0); \
    LDG_B(qb0, 0, K0); LDG_B(qb1, 1, K0); \
} while (0)
// packed 8-byte smem stores (1 STS.64 + 2 cvt.f16x2 per 4 floats)
#define ST_A(V, U, SB32) do { \
    int unit_ = tid + (U) * NT; \
    int r_ = unit_ >> 3, p_ = unit_ & 7; \
    uint32_t u0_, u1_; \
    PACK2(u0_, V.x, V.y); PACK2(u1_, V.z, V.w); \
    STS64((SB32) + AH_OFF + (r_ * SA + p_ * 4) * 2, u0_, u1_); \
} while (0)
#define ST_B(V, U, SB32) do { \
    int unit_ = tid + (U) * NT; \
    int r_ = unit_ >> 5, p_ = unit_ & 31; \
    uint32_t u0_, u1_; \
    PACK2(u0_, V.x, V.y); PACK2(u1_, V.z, V.w); \
    STS64((SB32) + BH_OFF + (r_ * SB + p_ * 4) * 2, u0_, u1_); \
} while (0)

    constexpr int nch = K / 32;     // 16 (mode 1) or 64 (mode 2); >= 2
    PREF_P(0);
    PREF_Q(32);

    for (int ch = 0; ch < nch; ch++) {
        const uint32_t sb32 = dyn0 + (ch & 1) * STAGE_BYTES;
        // drain the set holding chunk ch (P for even ch, Q for odd ch)
        if ((ch & 1) == 0) {
            ST_A(pa0, 0, sb32); ST_A(pa1, 1, sb32);
            ST_B(pb0, 0, sb32); ST_B(pb1, 1, sb32);
        } else {
            ST_A(qa0, 0, sb32); ST_A(qa1, 1, sb32);
            ST_B(qb0, 0, sb32); ST_B(qb1, 1, sb32);
        }
        __syncthreads();   // single barrier per chunk (double-buffered smem)

        // refill the just-freed set with chunk ch+2: ~2 chunk-times to complete
        if (ch + 2 < nch) {
            if ((ch & 1) == 0) PREF_P((ch + 2) * 32);
            else               PREF_Q((ch + 2) * 32);
        }

        const uint32_t sAh0 = sb32 + AH_OFF;
        const uint32_t sBh0 = sb32 + BH_OFF;

        #pragma unroll
        for (int kk = 0; kk < 32; kk += 16) {
            const uint32_t aoff = ((wm * 32 + (lane & 15)) * SA + kk + (lane >> 4) * 8) * 2;
            uint4 Ah0, Ah1;
            LDM_X4(Ah0.x, Ah0.y, Ah0.z, Ah0.w, sAh0 + aoff);
            LDM_X4(Ah1.x, Ah1.y, Ah1.z, Ah1.w, sAh0 + aoff + 16 * SA * 2);

            // B x4.trans: lanes 0-15 -> rows kk..kk+15 at col j, lanes 16-31 ->
            // same rows at col j+8; one op yields fragments for two n-columns.
            const uint32_t boff =
                ((kk + (lane & 15)) * SB + wn * 32 + ((lane >> 4) << 3)) * 2;
            uint2 Bh0, Bh1, Bh2, Bh3;
            LDM_X4T(Bh0.x, Bh0.y, Bh1.x, Bh1.y, sBh0 + boff);
            LDM_X4T(Bh2.x, Bh2.y, Bh3.x, Bh3.y, sBh0 + boff + 32);

            MMA1(c00, Ah0, Bh0); MMA1(c01, Ah0, Bh1);
            MMA1(c02, Ah0, Bh2); MMA1(c03, Ah0, Bh3);
            MMA1(c10, Ah1, Bh0); MMA1(c11, Ah1, Bh1);
            MMA1(c12, Ah1, Bh2); MMA1(c13, Ah1, Bh3);
        }
        // no trailing barrier: next chunk writes the OTHER smem buffer.
    }
#undef PREF_P
#undef PREF_Q
#undef LDG_A
#undef LDG_B
#undef ST_A
#undef ST_B

    // ---- epilogue ----
    const float* bptr = bias + (size_t)e * Ntot + n0;
#define EPI(C, I, J) do { \
    int r0_ = wm * 32 + (I) * 16 + (lane >> 2); \
    int s0_ = s_slot[r0_], s1_ = s_slot[r0_ + 8]; \
    int col_ = wn * 32 + (J) * 8 + (lane & 3) * 2; \
    float b0_ = bptr[col_], b1_ = bptr[col_ + 1]; \
    if (MODE == 1) { \
        if (s0_ >= 0) { \
            float2 o_ = make_float2(gelu_tanh(C.x + b0_), gelu_tanh(C.y + b1_)); \
            *(float2*)(g_h + (size_t)s0_ * HDIM + n0 + col_) = o_; \
        } \
        if (s1_ >= 0) { \
            float2 o_ = make_float2(gelu_tanh(C.z + b0_), gelu_tanh(C.w + b1_)); \
            *(float2*)(g_h + (size_t)s1_ * HDIM + n0 + col_) = o_; \
        } \
    } else { \
        if (s0_ >= 0) \
            *(float2*)(g_y + (size_t)s0_ * DIN + n0 + col_) = make_float2(C.x + b0_, C.y + b1_); \
        if (s1_ >= 0) \
            *(float2*)(g_y + (size_t)s1_ * DIN + n0 + col_) = make_float2(C.z + b0_, C.w + b1_); \
    } \
} while (0)
    EPI(c00, 0, 0); EPI(c01, 0, 1); EPI(c02, 0, 2); EPI(c03, 0, 3);
    EPI(c10, 1, 0); EPI(c11, 1, 1); EPI(c12, 1, 2); EPI(c13, 1, 3);
#undef EPI
}

// ---------------- combine + loss tail ----------------
__global__ void k_comb(const float* __restrict__ p, float* __restrict__ out) {
    int i = blockIdx.x * blockDim.x + threadIdx.x;
    if (i >= N_TOK * DIN / 4) return;
    int t = i / (DIN / 4);
    int d4 = i % (DIN / 4);
    float p0 = p[t * 2], p1 = p[t * 2 + 1];
    float4 y0 = *(const float4*)(g_y + (size_t)(2 * t) * DIN + d4 * 4);
    float4 y1 = *(const float4*)(g_y + (size_t)(2 * t + 1) * DIN + d4 * 4);
    float4 o;
    o.x = p0 * y0.x + p1 * y1.x;
    o.y = p0 * y0.y + p1 * y1.y;
    o.z = p0 * y0.z + p1 * y1.z;
    o.w = p0 * y0.w + p1 * y1.w;
    *(float4*)(out + (size_t)i * 4) = o;
}
__global__ void k_tail(float* __restrict__ out, int begin, int total) {
    int i = begin + blockIdx.x * blockDim.x + threadIdx.x;
    if (i < total) out[i] = 0.0f;
}

extern "C" void kernel_launch(void* const* d_in, const int* in_sizes, int n_in,
                              void* d_out, int out_size) {
    const float* x    = (const float*)d_in[0];
    const float* prob = (const float*)d_in[1];
    const void*  idx  = d_in[2];
    const float* W1   = (const float*)d_in[3];
    const float* b1   = (const float*)d_in[4];
    const float* W2   = (const float*)d_in[5];
    const float* b2   = (const float*)d_in[6];
    float* out = (float*)d_out;

    static int attr_done = 0;
    if (!attr_done) {
        cudaFuncSetAttribute(k_mma<1>, cudaFuncAttributeMaxDynamicSharedMemorySize, DSMEM);
        cudaFuncSetAttribute(k_mma<2>, cudaFuncAttributeMaxDynamicSharedMemorySize, DSMEM);
        attr_done = 1;
    }

    k_reset<<<1, 32>>>((const int*)idx);
    k_build<<<NSLOT / 256, 256>>>(idx);

    k_mma<1><<<dim3(HDIM / 128, NSLOT / 128, NEXP), NT, DSMEM>>>(x, W1, b1);
    k_mma<2><<<dim3(DIN / 128, NSLOT / 128, NEXP), NT, DSMEM>>>(nullptr, W2, b2);

    k_comb<<<(N_TOK * DIN / 4 + 255) / 256, 256>>>(prob, out);
    int tail = out_size - N_TOK * DIN;
    if (tail > 0)
        k_tail<<<(tail + 255) / 256, 256>>>(out, N_TOK * DIN, out_size);
    (void)in_sizes; (void)n_in;
}